// round 14
// baseline (speedup 1.0000x reference)
#include <cuda_runtime.h>
#include <cuda_bf16.h>
#include <cstdint>

#define P_SP 12544
#define CF 128
#define NB 16
#define NC 1000
#define EPSF 1e-6f
#define TPB 256
#define TPN 196
#define NTILES 3136
#define KS 288
#define KPAD 584
#define ROWB 1168
#define SX_OFF 149504
#define SACC_OFF 224256
#define SBIAS_OFF 224768
#define SM_TOTAL 225280

__device__ __align__(256) float    g_A[(size_t)NB * CF * P_SP];
__device__ __align__(256) uint16_t g_Xeh[(size_t)NB * 225 * 113 * 32];
__device__ __align__(256) uint16_t g_Xel[(size_t)NB * 225 * 113 * 32];
__device__ __align__(256) uint16_t g_Xoh[(size_t)NB * 225 * 112 * 32];
__device__ __align__(256) uint16_t g_Xol[(size_t)NB * 225 * 112 * 32];
__device__ float    g_Sp[(size_t)NB * CF * TPN];
__device__ float    g_S[NB * CF];
__device__ int      g_labels[NB * 2];
__device__ float    g_wgt[NB * 2 * CF];
__device__ __align__(256) float g_cam[(size_t)NB * 2 * P_SP];
__device__ unsigned g_mm[NB * 2 * 2];

__device__ __forceinline__ uint32_t s2u(const void* p) { return (uint32_t)__cvta_generic_to_shared(p); }
__device__ __forceinline__ void cp16f(uint32_t d, const void* s) {
    asm volatile("cp.async.cg.shared.global [%0], [%1], 16;" :: "r"(d), "l"(s));
}
#define CP_COMMIT() asm volatile("cp.async.commit_group;" ::: "memory")
#define CP_WAIT0()  asm volatile("cp.async.wait_group 0;" ::: "memory")
#define LDM4(r0,r1,r2,r3,addr) \
    asm volatile("ldmatrix.sync.aligned.m8n8.x4.shared.b16 {%0,%1,%2,%3}, [%4];" \
                 : "=r"(r0), "=r"(r1), "=r"(r2), "=r"(r3) : "r"(addr))
#define MMA16816(d0,d1,d2,d3,a0,a1,a2,a3,b0,b1) \
    asm volatile("mma.sync.aligned.m16n8k16.row.col.f32.bf16.bf16.f32 " \
                 "{%0,%1,%2,%3}, {%4,%5,%6,%7}, {%8,%9}, {%0,%1,%2,%3};" \
                 : "+f"(d0), "+f"(d1), "+f"(d2), "+f"(d3) \
                 : "r"(a0), "r"(a1), "r"(a2), "r"(a3), "r"(b0), "r"(b1))

// ---- 0) split x -> padded channel-last even/odd bf16 hi/lo ----
__global__ void split_kernel(const float* __restrict__ x) {
    const int y = blockIdx.x, n = blockIdx.y, t = threadIdx.x;
    if (t > 224) return;
    const bool inb = (y < 224) && (t < 224);
    const float* xs = x + ((size_t)n * 32 * 224 + y) * 224 + t;
    uint32_t hi[16], lo[16];
#pragma unroll
    for (int j = 0; j < 16; ++j) {
        float va = inb ? xs[(size_t)(2 * j) * 50176] : 0.f;
        float vb = inb ? xs[(size_t)(2 * j + 1) * 50176] : 0.f;
        __nv_bfloat16 ha = __float2bfloat16_rn(va), hb = __float2bfloat16_rn(vb);
        __nv_bfloat16 la = __float2bfloat16_rn(va - __bfloat162float(ha));
        __nv_bfloat16 lb = __float2bfloat16_rn(vb - __bfloat162float(hb));
        hi[j] = (uint32_t)__bfloat16_as_ushort(ha) | ((uint32_t)__bfloat16_as_ushort(hb) << 16);
        lo[j] = (uint32_t)__bfloat16_as_ushort(la) | ((uint32_t)__bfloat16_as_ushort(lb) << 16);
    }
    const int par = t & 1, x2 = t >> 1;
    const size_t idx = par ? ((size_t)(n * 225 + y) * 112 + x2) * 32
                           : ((size_t)(n * 225 + y) * 113 + x2) * 32;
    uint4* dh = (uint4*)((par ? g_Xoh : g_Xeh) + idx);
    uint4* dl = (uint4*)((par ? g_Xol : g_Xel) + idx);
#pragma unroll
    for (int q = 0; q < 4; ++q) {
        dh[q] = make_uint4(hi[4*q], hi[4*q+1], hi[4*q+2], hi[4*q+3]);
        dl[q] = make_uint4(lo[4*q], lo[4*q+1], lo[4*q+2], lo[4*q+3]);
    }
}

// fragment bundle for one kc (A hi/lo, B hi/lo)
struct Frags {
    uint32_t ah[2][4], al[2][4], bh[4][2], bl[4][2];
};
__device__ __forceinline__ void load_frags(Frags& f, const uint32_t* baseA,
                                           const uint32_t* baseB, uint32_t kb) {
#pragma unroll
    for (int mt = 0; mt < 2; ++mt) {
        LDM4(f.ah[mt][0], f.ah[mt][1], f.ah[mt][2], f.ah[mt][3], baseA[mt] + kb);
        LDM4(f.al[mt][0], f.al[mt][1], f.al[mt][2], f.al[mt][3], baseA[mt] + KS * 2 + kb);
    }
#pragma unroll
    for (int pp = 0; pp < 2; ++pp) {
        LDM4(f.bh[2*pp][0], f.bh[2*pp][1], f.bh[2*pp+1][0], f.bh[2*pp+1][1], baseB[pp] + kb);
        LDM4(f.bl[2*pp][0], f.bl[2*pp][1], f.bl[2*pp+1][0], f.bl[2*pp+1][1], baseB[pp] + KS * 2 + kb);
    }
}

// ---- 1) persistent mma.sync implicit-GEMM conv ----
__global__ void __launch_bounds__(TPB, 1) conv_mma_kernel(const float* __restrict__ Wc,
                                                          const float* __restrict__ bc) {
    extern __shared__ __align__(16) char dsm[];
    __nv_bfloat16* sW = (__nv_bfloat16*)dsm;
    __nv_bfloat16* sX = (__nv_bfloat16*)(dsm + SX_OFF);
    float* sacc  = (float*)(dsm + SACC_OFF);
    float* sbias = (float*)(dsm + SBIAS_OFF);
    const uint32_t smb = s2u(dsm);
    const int tid = threadIdx.x;
    const int wid = tid >> 5, lane = tid & 31;
    const int wm = wid >> 1, wn = wid & 1;
    const int gid = lane >> 2, tg = lane & 3;

    for (int idx = tid; idx < 128 * KS; idx += TPB) {
        const int f = idx / KS, k = idx - f * KS;
        const int tap = k >> 5, cin = k & 31;
        const float v = Wc[f * 288 + cin * 9 + tap];
        const __nv_bfloat16 wh = __float2bfloat16_rn(v);
        sW[f * KPAD + k] = wh;
        sW[f * KPAD + KS + k] = __float2bfloat16_rn(v - __bfloat162float(wh));
    }
    if (tid < 128) { sbias[tid] = bc[tid]; sacc[tid] = 0.f; }

    const int rselA = (lane & 7) + ((lane >> 3) & 1) * 8;
    const int cselA = (lane >> 4) * 8;
    uint32_t baseA[2];
#pragma unroll
    for (int mt = 0; mt < 2; ++mt)
        baseA[mt] = s2u(sW + (wm * 32 + mt * 16 + rselA) * KPAD + cselA);
    const int rselB = (lane & 7) + ((lane >> 4) & 1) * 8;
    const int cselB = ((lane >> 3) & 1) * 8;
    uint32_t baseB[2];
#pragma unroll
    for (int pp = 0; pp < 2; ++pp)
        baseB[pp] = s2u(sX + (wn * 32 + pp * 16 + rselB) * KPAD + cselB);

    for (int tile = blockIdx.x; tile < NTILES; tile += 148) {
        const int n = tile / TPN, ti = tile - n * TPN;
        const int p0 = ti * 64;

        // stage Xh + Xl (single group)
        for (int i = tid; i < 4608; i += TPB) {
            const int px = i / 72, r = i - px * 72;
            const int pass = r / 36, r2 = r - pass * 36;
            const int tap = r2 >> 2, q = r2 & 3;
            const int dy = tap / 3, dx = tap - dy * 3, par = dx & 1;
            const int p = p0 + px, oy = p / 112, ox = p - oy * 112;
            const int iy = 2 * oy + dy, x2 = ox + (dx >> 1), Wd = 113 - par;
            const uint16_t* arr = par ? (pass ? g_Xol : g_Xoh) : (pass ? g_Xel : g_Xeh);
            const uint16_t* sp = arr + ((size_t)(n * 225 + iy) * Wd + x2) * 32 + q * 8;
            cp16f(smb + SX_OFF + px * ROWB + pass * 576 + tap * 64 + q * 16, sp);
        }
        CP_COMMIT();

        float d[2][4][4];
#pragma unroll
        for (int mt = 0; mt < 2; ++mt)
#pragma unroll
            for (int nt = 0; nt < 4; ++nt)
#pragma unroll
                for (int e = 0; e < 4; ++e) d[mt][nt][e] = 0.f;

        CP_WAIT0();
        __syncthreads();

        // fused 3-product k-loop, register double-buffered fragments
        Frags fr[2];
        load_frags(fr[0], baseA, baseB, 0);
#pragma unroll 2
        for (int kc = 0; kc < KS; kc += 16) {
            const int cur = (kc >> 4) & 1;
            if (kc + 16 < KS) load_frags(fr[cur ^ 1], baseA, baseB, (uint32_t)(kc + 16) * 2);
            const Frags& f = fr[cur];
#pragma unroll
            for (int mt = 0; mt < 2; ++mt)
#pragma unroll
                for (int nt = 0; nt < 4; ++nt) {
                    MMA16816(d[mt][nt][0], d[mt][nt][1], d[mt][nt][2], d[mt][nt][3],
                             f.ah[mt][0], f.ah[mt][1], f.ah[mt][2], f.ah[mt][3],
                             f.bh[nt][0], f.bh[nt][1]);
                    MMA16816(d[mt][nt][0], d[mt][nt][1], d[mt][nt][2], d[mt][nt][3],
                             f.al[mt][0], f.al[mt][1], f.al[mt][2], f.al[mt][3],
                             f.bh[nt][0], f.bh[nt][1]);
                    MMA16816(d[mt][nt][0], d[mt][nt][1], d[mt][nt][2], d[mt][nt][3],
                             f.ah[mt][0], f.ah[mt][1], f.ah[mt][2], f.ah[mt][3],
                             f.bl[nt][0], f.bl[nt][1]);
                }
        }

        // epilogue: bias, store, deterministic GAP partials
#pragma unroll
        for (int mt = 0; mt < 2; ++mt) {
            const int fr0 = wm * 32 + mt * 16 + gid, fr1 = fr0 + 8;
            const float b0 = sbias[fr0], b1 = sbias[fr1];
            float* base0 = g_A + (size_t)(n * CF + fr0) * P_SP + p0 + wn * 32 + tg * 2;
            float* base1 = g_A + (size_t)(n * CF + fr1) * P_SP + p0 + wn * 32 + tg * 2;
            float s0 = 0.f, s1 = 0.f;
#pragma unroll
            for (int nt = 0; nt < 4; ++nt) {
                const float v0 = d[mt][nt][0] + b0, v1 = d[mt][nt][1] + b0;
                const float v2 = d[mt][nt][2] + b1, v3 = d[mt][nt][3] + b1;
                *(float2*)(base0 + nt * 8) = make_float2(v0, v1);
                *(float2*)(base1 + nt * 8) = make_float2(v2, v3);
                s0 += v0 + v1; s1 += v2 + v3;
            }
            s0 += __shfl_xor_sync(~0u, s0, 1); s0 += __shfl_xor_sync(~0u, s0, 2);
            s1 += __shfl_xor_sync(~0u, s1, 1); s1 += __shfl_xor_sync(~0u, s1, 2);
            if (tg == 0) { atomicAdd(&sacc[fr0], s0); atomicAdd(&sacc[fr1], s1); }
        }
        __syncthreads();
        if (tid < 128) {
            g_Sp[(size_t)(n * CF + tid) * TPN + ti] = sacc[tid];
            sacc[tid] = 0.f;
        }
        __syncthreads();
    }
}

// ---- tail ----
__global__ void gap_kernel() {
    const int idx = blockIdx.x * 256 + threadIdx.x;
    if (idx >= NB * CF) return;
    const float* p = g_Sp + (size_t)idx * TPN;
    float s = 0.f;
    for (int i = 0; i < TPN; ++i) s += p[i];
    g_S[idx] = s;
}
__global__ void logits_kernel(const float* __restrict__ Wf, const float* __restrict__ bf, float* __restrict__ out) {
    __shared__ float sS[NB * CF];
    const int tid = threadIdx.x;
    for (int i = tid; i < NB * CF; i += 256) sS[i] = g_S[i] * (1.f / 12544.f);
    __syncthreads();
    const int idx = blockIdx.x * 256 + tid;
    if (idx >= NB * NC) return;
    const int n = idx / NC, c = idx % NC;
    float acc = bf[c];
    const float4* wp = (const float4*)(Wf + (size_t)c * CF);
    const float4* s4 = (const float4*)(sS + n * CF);
#pragma unroll
    for (int q = 0; q < 32; ++q) {
        const float4 w = wp[q], s = s4[q];
        acc += s.x * w.x + s.y * w.y + s.z * w.z + s.w * w.w;
    }
    out[idx] = acc;
}
__global__ void topk_kernel(const float* __restrict__ logits) {
    const int n = blockIdx.x, tid = threadIdx.x;
    const float* lp = logits + n * NC;
    float v1 = -3.4e38f, v2 = -3.4e38f; int i1 = NC, i2 = NC;
    for (int c = tid; c < NC; c += 256) {
        const float v = lp[c];
        if (v > v1) { v2 = v1; i2 = i1; v1 = v; i1 = c; }
        else if (v > v2) { v2 = v; i2 = c; }
    }
    __shared__ float sv1[256], sv2[256]; __shared__ int si1[256], si2[256];
    sv1[tid] = v1; sv2[tid] = v2; si1[tid] = i1; si2[tid] = i2;
    __syncthreads();
    for (int s = 128; s; s >>= 1) {
        if (tid < s) {
            float a1 = sv1[tid], a2 = sv2[tid], b1 = sv1[tid+s], b2 = sv2[tid+s];
            int ja1 = si1[tid], ja2 = si2[tid], jb1 = si1[tid+s], jb2 = si2[tid+s];
            float f1, f2; int j1, j2;
            if (b1 > a1 || (b1 == a1 && jb1 < ja1)) {
                f1 = b1; j1 = jb1;
                if (a1 > b2 || (a1 == b2 && ja1 < jb2)) { f2 = a1; j2 = ja1; } else { f2 = b2; j2 = jb2; }
            } else {
                f1 = a1; j1 = ja1;
                if (b1 > a2 || (b1 == a2 && jb1 < ja2)) { f2 = b1; j2 = jb1; } else { f2 = a2; j2 = ja2; }
            }
            sv1[tid] = f1; sv2[tid] = f2; si1[tid] = j1; si2[tid] = j2;
        }
        __syncthreads();
    }
    if (tid == 0) { g_labels[n*2] = si1[0]; g_labels[n*2+1] = si2[0]; }
}
__global__ void wgt_kernel(const float* __restrict__ Wf) {
    const int nk = blockIdx.x, ch = threadIdx.x;
    if (ch == 0) { g_mm[nk*2] = 0x7f800000u; g_mm[nk*2+1] = 0u; }
    const int n = nk >> 1, l = g_labels[nk];
    const float g = Wf[(size_t)l * CF + ch] * (1.f / 12544.f);
    const float s = g_S[n * CF + ch];
    const float g2 = g * g;
    g_wgt[nk * CF + ch] = 12544.f * (g2 / (2.f * g2 + g2 * g * s + EPSF)) * fmaxf(g, 0.f);
}
__global__ void cam_kernel() {
    const int n = blockIdx.y, p = blockIdx.x * 256 + threadIdx.x;
    __shared__ float w0s[CF], w1s[CF];
    if (threadIdx.x < CF) {
        w0s[threadIdx.x] = g_wgt[(n*2+0)*CF + threadIdx.x];
        w1s[threadIdx.x] = g_wgt[(n*2+1)*CF + threadIdx.x];
    }
    __syncthreads();
    const float* Ap = g_A + (size_t)n * CF * P_SP + p;
    float a0 = 0.f, a1 = 0.f;
#pragma unroll 4
    for (int ch = 0; ch < CF; ++ch) { const float a = Ap[(size_t)ch * P_SP]; a0 += w0s[ch]*a; a1 += w1s[ch]*a; }
    const float c0 = fmaxf(a0, 0.f), c1 = fmaxf(a1, 0.f);
    g_cam[(size_t)(n*2+0)*P_SP + p] = c0;
    g_cam[(size_t)(n*2+1)*P_SP + p] = c1;
    float mn0 = c0, mx0 = c0, mn1 = c1, mx1 = c1;
#pragma unroll
    for (int o = 16; o; o >>= 1) {
        mn0 = fminf(mn0, __shfl_xor_sync(~0u, mn0, o)); mx0 = fmaxf(mx0, __shfl_xor_sync(~0u, mx0, o));
        mn1 = fminf(mn1, __shfl_xor_sync(~0u, mn1, o)); mx1 = fmaxf(mx1, __shfl_xor_sync(~0u, mx1, o));
    }
    __shared__ float smn0[8], smx0[8], smn1[8], smx1[8];
    const int w = threadIdx.x >> 5;
    if ((threadIdx.x & 31) == 0) { smn0[w]=mn0; smx0[w]=mx0; smn1[w]=mn1; smx1[w]=mx1; }
    __syncthreads();
    if (threadIdx.x == 0) {
        float a=smn0[0], b=smx0[0], c=smn1[0], d=smx1[0];
#pragma unroll
        for (int i = 1; i < 8; ++i) { a=fminf(a,smn0[i]); b=fmaxf(b,smx0[i]); c=fminf(c,smn1[i]); d=fmaxf(d,smx1[i]); }
        atomicMin(&g_mm[(n*2+0)*2+0], __float_as_uint(a)); atomicMax(&g_mm[(n*2+0)*2+1], __float_as_uint(b));
        atomicMin(&g_mm[(n*2+1)*2+0], __float_as_uint(c)); atomicMax(&g_mm[(n*2+1)*2+1], __float_as_uint(d));
    }
}
__global__ void final_kernel(float* __restrict__ out) {
    const int nk = blockIdx.x, tid = threadIdx.x;
    const float mn = __uint_as_float(g_mm[nk*2+0]);
    const float inv = 1.f / (__uint_as_float(g_mm[nk*2+1]) - mn + EPSF);
    const float* cm = g_cam + (size_t)nk * P_SP;
    int minx = 1<<29, miny = 1<<29, maxx = -1, maxy = -1, cnt = 0;
    float sum = 0.f;
    for (int p = tid; p < 224*224; p += 256) {
        const int dy = p / 224, dx = p % 224;
        float sy = fmaxf(0.5f*dy - 0.25f, 0.f), sx = fmaxf(0.5f*dx - 0.25f, 0.f);
        int iy = (int)sy; float fy = sy - iy; int iy1 = min(iy+1, 111);
        int ix = (int)sx; float fx = sx - ix; int ix1 = min(ix+1, 111);
        iy = min(iy, 111); ix = min(ix, 111);
        const float c00 = (cm[iy*112+ix]-mn)*inv,  c01 = (cm[iy*112+ix1]-mn)*inv;
        const float c10 = (cm[iy1*112+ix]-mn)*inv, c11 = (cm[iy1*112+ix1]-mn)*inv;
        const float v = (1.f-fy)*((1.f-fx)*c00 + fx*c01) + fy*((1.f-fx)*c10 + fx*c11);
        if (v >= 0.35f) { ++cnt; sum += v; minx = min(minx,dx); maxx = max(maxx,dx); miny = min(miny,dy); maxy = max(maxy,dy); }
    }
    __shared__ int ri[256]; __shared__ float rf[256];
    ri[tid]=minx; __syncthreads();
    for (int s=128;s;s>>=1){ if(tid<s) ri[tid]=min(ri[tid],ri[tid+s]); __syncthreads(); }
    minx=ri[0]; __syncthreads();
    ri[tid]=miny; __syncthreads();
    for (int s=128;s;s>>=1){ if(tid<s) ri[tid]=min(ri[tid],ri[tid+s]); __syncthreads(); }
    miny=ri[0]; __syncthreads();
    ri[tid]=maxx; __syncthreads();
    for (int s=128;s;s>>=1){ if(tid<s) ri[tid]=max(ri[tid],ri[tid+s]); __syncthreads(); }
    maxx=ri[0]; __syncthreads();
    ri[tid]=maxy; __syncthreads();
    for (int s=128;s;s>>=1){ if(tid<s) ri[tid]=max(ri[tid],ri[tid+s]); __syncthreads(); }
    maxy=ri[0]; __syncthreads();
    ri[tid]=cnt; __syncthreads();
    for (int s=128;s;s>>=1){ if(tid<s) ri[tid]+=ri[tid+s]; __syncthreads(); }
    cnt=ri[0]; __syncthreads();
    rf[tid]=sum; __syncthreads();
    for (int s=128;s;s>>=1){ if(tid<s) rf[tid]+=rf[tid+s]; __syncthreads(); }
    sum=rf[0];
    if (tid == 0) {
        const bool valid = (cnt > 0);
        float* boxes = out + 16000;
        boxes[nk*4+0] = valid ? (float)minx : -1.f;
        boxes[nk*4+1] = valid ? (float)miny : -1.f;
        boxes[nk*4+2] = valid ? (float)maxx : -1.f;
        boxes[nk*4+3] = valid ? (float)maxy : -1.f;
        out[16128+nk] = (float)g_labels[nk];
        out[16160+nk] = valid ? sum / (float)cnt : 0.f;
        out[16192+nk] = valid ? 1.f : 0.f;
    }
}

extern "C" void kernel_launch(void* const* d_in, const int* in_sizes, int n_in,
                              void* d_out, int out_size) {
    const float* x  = (const float*)d_in[0];
    const float* Wc = (const float*)d_in[1];
    const float* bc = (const float*)d_in[2];
    const float* Wf = (const float*)d_in[3];
    const float* bf = (const float*)d_in[4];
    float* out = (float*)d_out;
    cudaFuncSetAttribute(conv_mma_kernel, cudaFuncAttributeMaxDynamicSharedMemorySize, SM_TOTAL);
    split_kernel<<<dim3(225, NB), 256>>>(x);
    conv_mma_kernel<<<148, TPB, SM_TOTAL>>>(Wc, bc);
    gap_kernel<<<8, 256>>>();
    logits_kernel<<<(NB * NC + 255) / 256, 256>>>(Wf, bf, out);
    topk_kernel<<<NB, 256>>>(out);
    wgt_kernel<<<NB * 2, CF>>>(Wf);
    cam_kernel<<<dim3(49, NB), 256>>>();
    final_kernel<<<NB * 2, 256>>>(out);
}

// round 16
// speedup vs baseline: 1.1176x; 1.1176x over previous
#include <cuda_runtime.h>
#include <cuda_bf16.h>
#include <cstdint>

#define P_SP 12544
#define CF 128
#define NB 16
#define NC 1000
#define EPSF 1e-6f
#define TPB 256
#define TPN 196
#define NTILES 3136
#define KS 288
#define KPAD 584
#define ROWB 1168
#define SX_OFF 149504
#define SACC_OFF 224256
#define SBIAS_OFF 224768
#define SM_TOTAL 225280

__device__ __align__(256) float    g_A[(size_t)NB * CF * P_SP];
__device__ __align__(256) uint16_t g_Xeh[(size_t)NB * 225 * 113 * 32];
__device__ __align__(256) uint16_t g_Xel[(size_t)NB * 225 * 113 * 32];
__device__ __align__(256) uint16_t g_Xoh[(size_t)NB * 225 * 112 * 32];
__device__ __align__(256) uint16_t g_Xol[(size_t)NB * 225 * 112 * 32];
__device__ float    g_Sp[(size_t)NB * CF * TPN];
__device__ float    g_S[NB * CF];
__device__ int      g_labels[NB * 2];
__device__ float    g_wgt[NB * 2 * CF];
__device__ __align__(256) float g_cam[(size_t)NB * 2 * P_SP];
__device__ unsigned g_mm[NB * 2 * 2];

__device__ __forceinline__ uint32_t s2u(const void* p) { return (uint32_t)__cvta_generic_to_shared(p); }
__device__ __forceinline__ void cp16f(uint32_t d, const void* s) {
    asm volatile("cp.async.cg.shared.global [%0], [%1], 16;" :: "r"(d), "l"(s));
}
#define CP_COMMIT() asm volatile("cp.async.commit_group;" ::: "memory")
#define CP_WAIT1()  asm volatile("cp.async.wait_group 1;" ::: "memory")
#define CP_WAIT0()  asm volatile("cp.async.wait_group 0;" ::: "memory")
#define LDM4(r0,r1,r2,r3,addr) \
    asm volatile("ldmatrix.sync.aligned.m8n8.x4.shared.b16 {%0,%1,%2,%3}, [%4];" \
                 : "=r"(r0), "=r"(r1), "=r"(r2), "=r"(r3) : "r"(addr))
#define MMA16816(d,a,b0,b1) \
    asm volatile("mma.sync.aligned.m16n8k16.row.col.f32.bf16.bf16.f32 " \
                 "{%0,%1,%2,%3}, {%4,%5,%6,%7}, {%8,%9}, {%0,%1,%2,%3};" \
                 : "+f"((d)[0]), "+f"((d)[1]), "+f"((d)[2]), "+f"((d)[3]) \
                 : "r"((a)[0]), "r"((a)[1]), "r"((a)[2]), "r"((a)[3]), "r"(b0), "r"(b1))

// ---- 0) split x -> padded channel-last even/odd bf16 hi/lo ----
__global__ void split_kernel(const float* __restrict__ x) {
    const int y = blockIdx.x, n = blockIdx.y, t = threadIdx.x;
    if (t > 224) return;
    const bool inb = (y < 224) && (t < 224);
    const float* xs = x + ((size_t)n * 32 * 224 + y) * 224 + t;
    uint32_t hi[16], lo[16];
#pragma unroll
    for (int j = 0; j < 16; ++j) {
        float va = inb ? xs[(size_t)(2 * j) * 50176] : 0.f;
        float vb = inb ? xs[(size_t)(2 * j + 1) * 50176] : 0.f;
        __nv_bfloat16 ha = __float2bfloat16_rn(va), hb = __float2bfloat16_rn(vb);
        __nv_bfloat16 la = __float2bfloat16_rn(va - __bfloat162float(ha));
        __nv_bfloat16 lb = __float2bfloat16_rn(vb - __bfloat162float(hb));
        hi[j] = (uint32_t)__bfloat16_as_ushort(ha) | ((uint32_t)__bfloat16_as_ushort(hb) << 16);
        lo[j] = (uint32_t)__bfloat16_as_ushort(la) | ((uint32_t)__bfloat16_as_ushort(lb) << 16);
    }
    const int par = t & 1, x2 = t >> 1;
    const size_t idx = par ? ((size_t)(n * 225 + y) * 112 + x2) * 32
                           : ((size_t)(n * 225 + y) * 113 + x2) * 32;
    uint4* dh = (uint4*)((par ? g_Xoh : g_Xeh) + idx);
    uint4* dl = (uint4*)((par ? g_Xol : g_Xel) + idx);
#pragma unroll
    for (int q = 0; q < 4; ++q) {
        dh[q] = make_uint4(hi[4*q], hi[4*q+1], hi[4*q+2], hi[4*q+3]);
        dl[q] = make_uint4(lo[4*q], lo[4*q+1], lo[4*q+2], lo[4*q+3]);
    }
}

// ---- 1) persistent mma.sync implicit-GEMM conv ----
__global__ void __launch_bounds__(TPB, 1) conv_mma_kernel(const float* __restrict__ Wc,
                                                          const float* __restrict__ bc) {
    extern __shared__ __align__(16) char dsm[];
    __nv_bfloat16* sW = (__nv_bfloat16*)dsm;
    __nv_bfloat16* sX = (__nv_bfloat16*)(dsm + SX_OFF);
    float* sacc  = (float*)(dsm + SACC_OFF);
    float* sbias = (float*)(dsm + SBIAS_OFF);
    const uint32_t smb = s2u(dsm);
    const int tid = threadIdx.x;
    const int wid = tid >> 5, lane = tid & 31;
    const int wm = wid >> 1, wn = wid & 1;
    const int gid = lane >> 2, tg = lane & 3;

    for (int idx = tid; idx < 128 * KS; idx += TPB) {
        const int f = idx / KS, k = idx - f * KS;
        const int tap = k >> 5, cin = k & 31;
        const float v = Wc[f * 288 + cin * 9 + tap];
        const __nv_bfloat16 wh = __float2bfloat16_rn(v);
        sW[f * KPAD + k] = wh;
        sW[f * KPAD + KS + k] = __float2bfloat16_rn(v - __bfloat162float(wh));
    }
    if (tid < 128) { sbias[tid] = bc[tid]; sacc[tid] = 0.f; }

    const int rselA = (lane & 7) + ((lane >> 3) & 1) * 8;
    const int cselA = (lane >> 4) * 8;
    uint32_t baseA[2];
#pragma unroll
    for (int mt = 0; mt < 2; ++mt)
        baseA[mt] = s2u(sW + (wm * 32 + mt * 16 + rselA) * KPAD + cselA);
    const int rselB = (lane & 7) + ((lane >> 4) & 1) * 8;
    const int cselB = ((lane >> 3) & 1) * 8;
    uint32_t baseB[2];
#pragma unroll
    for (int pp = 0; pp < 2; ++pp)
        baseB[pp] = s2u(sX + (wn * 32 + pp * 16 + rselB) * KPAD + cselB);

    for (int tile = blockIdx.x; tile < NTILES; tile += 148) {
        const int n = tile / TPN, ti = tile - n * TPN;
        const int p0 = ti * 64;

        // stage Xh (group 0) then Xl (group 1)
#pragma unroll 1
        for (int pass = 0; pass < 2; ++pass) {
            for (int i = tid; i < 2304; i += TPB) {
                const int px = i / 36, r2 = i - px * 36;
                const int tap = r2 >> 2, q = r2 & 3;
                const int dy = tap / 3, dx = tap - dy * 3, par = dx & 1;
                const int p = p0 + px, oy = p / 112, ox = p - oy * 112;
                const int iy = 2 * oy + dy, x2 = ox + (dx >> 1), Wd = 113 - par;
                const uint16_t* arr = par ? (pass ? g_Xol : g_Xoh) : (pass ? g_Xel : g_Xeh);
                const uint16_t* sp = arr + ((size_t)(n * 225 + iy) * Wd + x2) * 32 + q * 8;
                cp16f(smb + SX_OFF + px * ROWB + pass * 576 + tap * 64 + q * 16, sp);
            }
            CP_COMMIT();
        }

        float d[2][4][4];
#pragma unroll
        for (int mt = 0; mt < 2; ++mt)
#pragma unroll
            for (int nt = 0; nt < 4; ++nt)
#pragma unroll
                for (int e = 0; e < 4; ++e) d[mt][nt][e] = 0.f;

        CP_WAIT1();          // Xh resident
        __syncthreads();

        // pass A: (Wh + Wl) x Xh — B fragments loaded once per kc
#pragma unroll 2
        for (int kc = 0; kc < KS; kc += 16) {
            const uint32_t kb = (uint32_t)kc * 2;
            uint32_t ah[2][4], al[2][4], b[4][2];
#pragma unroll
            for (int mt = 0; mt < 2; ++mt) {
                LDM4(ah[mt][0], ah[mt][1], ah[mt][2], ah[mt][3], baseA[mt] + kb);
                LDM4(al[mt][0], al[mt][1], al[mt][2], al[mt][3], baseA[mt] + KS * 2 + kb);
            }
#pragma unroll
            for (int pp = 0; pp < 2; ++pp)
                LDM4(b[2*pp][0], b[2*pp][1], b[2*pp+1][0], b[2*pp+1][1], baseB[pp] + kb);
#pragma unroll
            for (int mt = 0; mt < 2; ++mt)
#pragma unroll
                for (int nt = 0; nt < 4; ++nt) {
                    MMA16816(d[mt][nt], ah[mt], b[nt][0], b[nt][1]);
                    MMA16816(d[mt][nt], al[mt], b[nt][0], b[nt][1]);
                }
        }

        CP_WAIT0();          // Xl resident
        __syncthreads();

        // pass B: Wh x Xl
#pragma unroll 2
        for (int kc = 0; kc < KS; kc += 16) {
            const uint32_t kb = (uint32_t)kc * 2;
            uint32_t a[2][4], b[4][2];
#pragma unroll
            for (int mt = 0; mt < 2; ++mt)
                LDM4(a[mt][0], a[mt][1], a[mt][2], a[mt][3], baseA[mt] + kb);
#pragma unroll
            for (int pp = 0; pp < 2; ++pp)
                LDM4(b[2*pp][0], b[2*pp][1], b[2*pp+1][0], b[2*pp+1][1],
                     baseB[pp] + KS * 2 + kb);
#pragma unroll
            for (int mt = 0; mt < 2; ++mt)
#pragma unroll
                for (int nt = 0; nt < 4; ++nt)
                    MMA16816(d[mt][nt], a[mt], b[nt][0], b[nt][1]);
        }

        // epilogue: bias, store, deterministic GAP partials
#pragma unroll
        for (int mt = 0; mt < 2; ++mt) {
            const int fr0 = wm * 32 + mt * 16 + gid, fr1 = fr0 + 8;
            const float b0 = sbias[fr0], b1 = sbias[fr1];
            float* base0 = g_A + (size_t)(n * CF + fr0) * P_SP + p0 + wn * 32 + tg * 2;
            float* base1 = g_A + (size_t)(n * CF + fr1) * P_SP + p0 + wn * 32 + tg * 2;
            float s0 = 0.f, s1 = 0.f;
#pragma unroll
            for (int nt = 0; nt < 4; ++nt) {
                const float v0 = d[mt][nt][0] + b0, v1 = d[mt][nt][1] + b0;
                const float v2 = d[mt][nt][2] + b1, v3 = d[mt][nt][3] + b1;
                *(float2*)(base0 + nt * 8) = make_float2(v0, v1);
                *(float2*)(base1 + nt * 8) = make_float2(v2, v3);
                s0 += v0 + v1; s1 += v2 + v3;
            }
            s0 += __shfl_xor_sync(~0u, s0, 1); s0 += __shfl_xor_sync(~0u, s0, 2);
            s1 += __shfl_xor_sync(~0u, s1, 1); s1 += __shfl_xor_sync(~0u, s1, 2);
            if (tg == 0) { atomicAdd(&sacc[fr0], s0); atomicAdd(&sacc[fr1], s1); }
        }
        __syncthreads();
        if (tid < 128) {
            g_Sp[(size_t)(n * CF + tid) * TPN + ti] = sacc[tid];
            sacc[tid] = 0.f;
        }
    }
}

// ---- tail ----
__global__ void gap_kernel() {
    const int idx = blockIdx.x * 256 + threadIdx.x;
    if (idx >= NB * CF) return;
    const float* p = g_Sp + (size_t)idx * TPN;
    float s = 0.f;
    for (int i = 0; i < TPN; ++i) s += p[i];
    g_S[idx] = s;
}
__global__ void logits_kernel(const float* __restrict__ Wf, const float* __restrict__ bf, float* __restrict__ out) {
    __shared__ float sS[NB * CF];
    const int tid = threadIdx.x;
    for (int i = tid; i < NB * CF; i += 256) sS[i] = g_S[i] * (1.f / 12544.f);
    __syncthreads();
    const int idx = blockIdx.x * 256 + tid;
    if (idx >= NB * NC) return;
    const int n = idx / NC, c = idx % NC;
    float acc = bf[c];
    const float4* wp = (const float4*)(Wf + (size_t)c * CF);
    const float4* s4 = (const float4*)(sS + n * CF);
#pragma unroll
    for (int q = 0; q < 32; ++q) {
        const float4 w = wp[q], s = s4[q];
        acc += s.x * w.x + s.y * w.y + s.z * w.z + s.w * w.w;
    }
    out[idx] = acc;
}
__global__ void topk_kernel(const float* __restrict__ logits) {
    const int n = blockIdx.x, tid = threadIdx.x;
    const float* lp = logits + n * NC;
    float v1 = -3.4e38f, v2 = -3.4e38f; int i1 = NC, i2 = NC;
    for (int c = tid; c < NC; c += 256) {
        const float v = lp[c];
        if (v > v1) { v2 = v1; i2 = i1; v1 = v; i1 = c; }
        else if (v > v2) { v2 = v; i2 = c; }
    }
    __shared__ float sv1[256], sv2[256]; __shared__ int si1[256], si2[256];
    sv1[tid] = v1; sv2[tid] = v2; si1[tid] = i1; si2[tid] = i2;
    __syncthreads();
    for (int s = 128; s; s >>= 1) {
        if (tid < s) {
            float a1 = sv1[tid], a2 = sv2[tid], b1 = sv1[tid+s], b2 = sv2[tid+s];
            int ja1 = si1[tid], ja2 = si2[tid], jb1 = si1[tid+s], jb2 = si2[tid+s];
            float f1, f2; int j1, j2;
            if (b1 > a1 || (b1 == a1 && jb1 < ja1)) {
                f1 = b1; j1 = jb1;
                if (a1 > b2 || (a1 == b2 && ja1 < jb2)) { f2 = a1; j2 = ja1; } else { f2 = b2; j2 = jb2; }
            } else {
                f1 = a1; j1 = ja1;
                if (b1 > a2 || (b1 == a2 && jb1 < ja2)) { f2 = b1; j2 = jb1; } else { f2 = a2; j2 = ja2; }
            }
            sv1[tid] = f1; sv2[tid] = f2; si1[tid] = j1; si2[tid] = j2;
        }
        __syncthreads();
    }
    if (tid == 0) { g_labels[n*2] = si1[0]; g_labels[n*2+1] = si2[0]; }
}
__global__ void wgt_kernel(const float* __restrict__ Wf) {
    const int nk = blockIdx.x, ch = threadIdx.x;
    if (ch == 0) { g_mm[nk*2] = 0x7f800000u; g_mm[nk*2+1] = 0u; }
    const int n = nk >> 1, l = g_labels[nk];
    const float g = Wf[(size_t)l * CF + ch] * (1.f / 12544.f);
    const float s = g_S[n * CF + ch];
    const float g2 = g * g;
    g_wgt[nk * CF + ch] = 12544.f * (g2 / (2.f * g2 + g2 * g * s + EPSF)) * fmaxf(g, 0.f);
}
__global__ void cam_kernel() {
    const int n = blockIdx.y, p = blockIdx.x * 256 + threadIdx.x;
    __shared__ float w0s[CF], w1s[CF];
    if (threadIdx.x < CF) {
        w0s[threadIdx.x] = g_wgt[(n*2+0)*CF + threadIdx.x];
        w1s[threadIdx.x] = g_wgt[(n*2+1)*CF + threadIdx.x];
    }
    __syncthreads();
    const float* Ap = g_A + (size_t)n * CF * P_SP + p;
    float a0 = 0.f, a1 = 0.f;
#pragma unroll 4
    for (int ch = 0; ch < CF; ++ch) { const float a = Ap[(size_t)ch * P_SP]; a0 += w0s[ch]*a; a1 += w1s[ch]*a; }
    const float c0 = fmaxf(a0, 0.f), c1 = fmaxf(a1, 0.f);
    g_cam[(size_t)(n*2+0)*P_SP + p] = c0;
    g_cam[(size_t)(n*2+1)*P_SP + p] = c1;
    float mn0 = c0, mx0 = c0, mn1 = c1, mx1 = c1;
#pragma unroll
    for (int o = 16; o; o >>= 1) {
        mn0 = fminf(mn0, __shfl_xor_sync(~0u, mn0, o)); mx0 = fmaxf(mx0, __shfl_xor_sync(~0u, mx0, o));
        mn1 = fminf(mn1, __shfl_xor_sync(~0u, mn1, o)); mx1 = fmaxf(mx1, __shfl_xor_sync(~0u, mx1, o));
    }
    __shared__ float smn0[8], smx0[8], smn1[8], smx1[8];
    const int w = threadIdx.x >> 5;
    if ((threadIdx.x & 31) == 0) { smn0[w]=mn0; smx0[w]=mx0; smn1[w]=mn1; smx1[w]=mx1; }
    __syncthreads();
    if (threadIdx.x == 0) {
        float a=smn0[0], b=smx0[0], c=smn1[0], d=smx1[0];
#pragma unroll
        for (int i = 1; i < 8; ++i) { a=fminf(a,smn0[i]); b=fmaxf(b,smx0[i]); c=fminf(c,smn1[i]); d=fmaxf(d,smx1[i]); }
        atomicMin(&g_mm[(n*2+0)*2+0], __float_as_uint(a)); atomicMax(&g_mm[(n*2+0)*2+1], __float_as_uint(b));
        atomicMin(&g_mm[(n*2+1)*2+0], __float_as_uint(c)); atomicMax(&g_mm[(n*2+1)*2+1], __float_as_uint(d));
    }
}
__global__ void final_kernel(float* __restrict__ out) {
    const int nk = blockIdx.x, tid = threadIdx.x;
    const float mn = __uint_as_float(g_mm[nk*2+0]);
    const float inv = 1.f / (__uint_as_float(g_mm[nk*2+1]) - mn + EPSF);
    const float* cm = g_cam + (size_t)nk * P_SP;
    int minx = 1<<29, miny = 1<<29, maxx = -1, maxy = -1, cnt = 0;
    float sum = 0.f;
    for (int p = tid; p < 224*224; p += 256) {
        const int dy = p / 224, dx = p % 224;
        float sy = fmaxf(0.5f*dy - 0.25f, 0.f), sx = fmaxf(0.5f*dx - 0.25f, 0.f);
        int iy = (int)sy; float fy = sy - iy; int iy1 = min(iy+1, 111);
        int ix = (int)sx; float fx = sx - ix; int ix1 = min(ix+1, 111);
        iy = min(iy, 111); ix = min(ix, 111);
        const float c00 = (cm[iy*112+ix]-mn)*inv,  c01 = (cm[iy*112+ix1]-mn)*inv;
        const float c10 = (cm[iy1*112+ix]-mn)*inv, c11 = (cm[iy1*112+ix1]-mn)*inv;
        const float v = (1.f-fy)*((1.f-fx)*c00 + fx*c01) + fy*((1.f-fx)*c10 + fx*c11);
        if (v >= 0.35f) { ++cnt; sum += v; minx = min(minx,dx); maxx = max(maxx,dx); miny = min(miny,dy); maxy = max(maxy,dy); }
    }
    __shared__ int ri[256]; __shared__ float rf[256];
    ri[tid]=minx; __syncthreads();
    for (int s=128;s;s>>=1){ if(tid<s) ri[tid]=min(ri[tid],ri[tid+s]); __syncthreads(); }
    minx=ri[0]; __syncthreads();
    ri[tid]=miny; __syncthreads();
    for (int s=128;s;s>>=1){ if(tid<s) ri[tid]=min(ri[tid],ri[tid+s]); __syncthreads(); }
    miny=ri[0]; __syncthreads();
    ri[tid]=maxx; __syncthreads();
    for (int s=128;s;s>>=1){ if(tid<s) ri[tid]=max(ri[tid],ri[tid+s]); __syncthreads(); }
    maxx=ri[0]; __syncthreads();
    ri[tid]=maxy; __syncthreads();
    for (int s=128;s;s>>=1){ if(tid<s) ri[tid]=max(ri[tid],ri[tid+s]); __syncthreads(); }
    maxy=ri[0]; __syncthreads();
    ri[tid]=cnt; __syncthreads();
    for (int s=128;s;s>>=1){ if(tid<s) ri[tid]+=ri[tid+s]; __syncthreads(); }
    cnt=ri[0]; __syncthreads();
    rf[tid]=sum; __syncthreads();
    for (int s=128;s;s>>=1){ if(tid<s) rf[tid]+=rf[tid+s]; __syncthreads(); }
    sum=rf[0];
    if (tid == 0) {
        const bool valid = (cnt > 0);
        float* boxes = out + 16000;
        boxes[nk*4+0] = valid ? (float)minx : -1.f;
        boxes[nk*4+1] = valid ? (float)miny : -1.f;
        boxes[nk*4+2] = valid ? (float)maxx : -1.f;
        boxes[nk*4+3] = valid ? (float)maxy : -1.f;
        out[16128+nk] = (float)g_labels[nk];
        out[16160+nk] = valid ? sum / (float)cnt : 0.f;
        out[16192+nk] = valid ? 1.f : 0.f;
    }
}

extern "C" void kernel_launch(void* const* d_in, const int* in_sizes, int n_in,
                              void* d_out, int out_size) {
    const float* x  = (const float*)d_in[0];
    const float* Wc = (const float*)d_in[1];
    const float* bc = (const float*)d_in[2];
    const float* Wf = (const float*)d_in[3];
    const float* bf = (const float*)d_in[4];
    float* out = (float*)d_out;
    cudaFuncSetAttribute(conv_mma_kernel, cudaFuncAttributeMaxDynamicSharedMemorySize, SM_TOTAL);
    split_kernel<<<dim3(225, NB), 256>>>(x);
    conv_mma_kernel<<<148, TPB, SM_TOTAL>>>(Wc, bc);
    gap_kernel<<<8, 256>>>();
    logits_kernel<<<(NB * NC + 255) / 256, 256>>>(Wf, bf, out);
    topk_kernel<<<NB, 256>>>(out);
    wgt_kernel<<<NB * 2, CF>>>(Wf);
    cam_kernel<<<dim3(49, NB), 256>>>();
    final_kernel<<<NB * 2, 256>>>(out);
}